// round 14
// baseline (speedup 1.0000x reference)
#include <cuda_runtime.h>
#include <cuda_fp16.h>
#include <math.h>
#include <stdint.h>

#define BATCH 512
#define TSEQ  256
#define DIN   128
#define HID   256
#define G4    1024
#define FDIM  64
#define EDIM  320
#define DM    384
#define NMERG 394
#define NL1   512
#define NACT  8

#define NBLK  128    // 16 clusters x 8 blocks
#define CSIZE 8

// smem layout (dynamic): [0:16) mbar[2] | [16:33808) sH[2][32][264] fp16 | [33808:51216) sX[2][32][136] fp16
#define SMEM_TOTAL 51216
#define SH_OFF 16
#define SX_OFF 33808

// ---------------- scratch (static device memory; no allocations) ----------------
__device__ __half d_hs[33554432];      // [B, T, H] fp16 hidden states
__device__ float d_sf[BATCH * EDIM];   // state_full
__device__ float d_qk[BATCH * HID];
__device__ float d_Mkp[EDIM * HID];    // Wk @ proj_W
__device__ float d_MA1[EDIM * HID];    // Wv @ proj_W
__device__ float d_Amat[EDIM * HID];   // Wo @ Wv @ proj_W
__device__ float d_P[EDIM * HID];      // Wq^T @ Mkp
__device__ float d_cqk[HID];           // bq @ Mkp
__device__ float d_aconst[EDIM];
__device__ float d_hbar[BATCH * HID];
__device__ float d_merged[BATCH * NMERG];  // [attn_out | s | qfeat]
__device__ float d_x1[BATCH * NL1];

// ---------------- helpers ----------------
__device__ __forceinline__ uint32_t smem_u32(const void* p) {
    uint32_t a;
    asm("{ .reg .u64 t; cvta.to.shared.u64 t, %1; cvt.u32.u64 %0, t; }" : "=r"(a) : "l"(p));
    return a;
}
__device__ __forceinline__ uint32_t mapa_u32(uint32_t addr, uint32_t rank) {
    uint32_t r;
    asm("mapa.shared::cluster.u32 %0, %1, %2;" : "=r"(r) : "r"(addr), "r"(rank));
    return r;
}
__device__ __forceinline__ void st_async_b32(uint32_t dst, uint32_t val, uint32_t mbar) {
    asm volatile("st.async.shared::cluster.mbarrier::complete_tx::bytes.b32 [%0], %1, [%2];"
                 :: "r"(dst), "r"(val), "r"(mbar) : "memory");
}
#define MBAR_INIT(a, n) asm volatile("mbarrier.init.shared.b64 [%0], %1;" :: "r"(a), "r"(n) : "memory")
#define MBAR_EXPECT_TX(a, tx) asm volatile("mbarrier.arrive.expect_tx.shared.b64 _, [%0], %1;" :: "r"(a), "r"(tx) : "memory")
#define MBAR_WAIT(a, ph) do { \
    uint32_t _mb = (a); uint32_t _p = (ph); uint32_t _done; \
    asm volatile("{\n\t.reg .pred p;\n\tmbarrier.try_wait.parity.acquire.cta.shared::cta.b64 p, [%1], %2;\n\tselp.b32 %0, 1, 0, p;\n\t}" \
        : "=r"(_done) : "r"(_mb), "r"(_p) : "memory"); \
    if (!_done) { \
        asm volatile("{\n\t.reg .pred P1;\n\tWL_%=:\n\tmbarrier.try_wait.parity.acquire.cta.shared::cta.b64 P1, [%0], %1, 0x989680;\n\t@P1 bra.uni WD_%=;\n\tbra.uni WL_%=;\n\tWD_%=:\n\t}" \
            :: "r"(_mb), "r"(_p) : "memory"); \
    } \
} while (0)
#define CLUSTER_SYNC() do { \
    asm volatile("barrier.cluster.arrive.aligned;" ::: "memory"); \
    asm volatile("barrier.cluster.wait.aligned;" ::: "memory"); \
} while (0)

__device__ __forceinline__ uint32_t pack_h2(float x, float y) {
    __half2 t = __floats2half2_rn(x, y);
    return *reinterpret_cast<uint32_t*>(&t);
}
__device__ __forceinline__ void mma_f16(float* c, uint32_t a0, uint32_t a1,
                                        uint32_t a2, uint32_t a3,
                                        uint32_t b0, uint32_t b1) {
    asm volatile("mma.sync.aligned.m16n8k16.row.col.f32.f16.f16.f32 "
        "{%0,%1,%2,%3}, {%4,%5,%6,%7}, {%8,%9}, {%0,%1,%2,%3};"
        : "+f"(c[0]), "+f"(c[1]), "+f"(c[2]), "+f"(c[3])
        : "r"(a0), "r"(a1), "r"(a2), "r"(a3), "r"(b0), "r"(b1));
}
__device__ __forceinline__ float fsig(float x) {
    return __fdividef(1.f, 1.f + __expf(-x));
}
__device__ __forceinline__ float ftanh(float x) {
    return 2.f * fsig(2.f * x) - 1.f;
}

// ---------------- 64x64 fp32 tile GEMM (device; precompose) --------------------------
__device__ void tile64(const float* __restrict__ A, int lda, bool transA,
                       const float* __restrict__ B, int ldb,
                       float* __restrict__ C, int ldc, int K, int tid,
                       float (*sA)[68], float (*sW)[68]) {
    int tx = tid & 15, ty = tid >> 4;
    float acc[4][4] = {};
    for (int k0 = 0; k0 < K; k0 += 16) {
        #pragma unroll
        for (int i = 0; i < 4; i++) {
            int idx = tid + i * 256;
            int r = idx >> 4, k = idx & 15;
            sA[k][r] = transA ? A[(size_t)(k0 + k) * lda + r]
                              : A[(size_t)r * lda + k0 + k];
            sW[k][r] = B[(size_t)(k0 + k) * ldb + r];
        }
        __syncthreads();
        #pragma unroll
        for (int k = 0; k < 16; k++) {
            float4 a = *(const float4*)&sA[k][ty * 4];
            float4 b = *(const float4*)&sW[k][tx * 4];
            acc[0][0] += a.x * b.x; acc[0][1] += a.x * b.y; acc[0][2] += a.x * b.z; acc[0][3] += a.x * b.w;
            acc[1][0] += a.y * b.x; acc[1][1] += a.y * b.y; acc[1][2] += a.y * b.z; acc[1][3] += a.y * b.w;
            acc[2][0] += a.z * b.x; acc[2][1] += a.z * b.y; acc[2][2] += a.z * b.z; acc[2][3] += a.z * b.w;
            acc[3][0] += a.w * b.x; acc[3][1] += a.w * b.y; acc[3][2] += a.w * b.z; acc[3][3] += a.w * b.w;
        }
        __syncthreads();
    }
    #pragma unroll
    for (int r = 0; r < 4; r++)
        #pragma unroll
        for (int cc = 0; cc < 4; cc++)
            C[(size_t)(ty * 4 + r) * ldc + tx * 4 + cc] = acc[r][cc];
}

// ---------------- persistent fused LSTM: DSMEM cluster h-exchange --------------------
// 16 clusters of 8. Block = 32 batch rows x 128 gate cols; h broadcast to all 8
// cluster peers via st.async into their smem h-tile + mbarrier tx accounting.
// Cluster 0 additionally runs the attention weight precompose before its recurrence.
extern __shared__ char smem_raw[];
__global__ __launch_bounds__(256, 1) __cluster_dims__(CSIZE, 1, 1)
void lstm_persist(
    const float* __restrict__ X, const float* __restrict__ W_ih,
    const float* __restrict__ W_hh, const float* __restrict__ b_ih,
    const float* __restrict__ b_hh, __half* __restrict__ hs,
    const float* __restrict__ in_proj_W, const float* __restrict__ in_proj_b,
    const float* __restrict__ proj_W, const float* __restrict__ proj_b,
    const float* __restrict__ out_proj_W, const float* __restrict__ out_proj_b,
    float* __restrict__ Mkp, float* __restrict__ MA1, float* __restrict__ Amat,
    float* __restrict__ P, float* __restrict__ cqk, float* __restrict__ aconst)
{
    int tid = threadIdx.x;
    int rank = blockIdx.x & 7;      // col tile / cluster rank
    int gid  = blockIdx.x >> 3;     // batch group / cluster id
    int n0 = rank * 128, m0 = gid * 32;

    uint32_t sbase = smem_u32(smem_raw);
    __half* sH = (__half*)(smem_raw + SH_OFF);   // [2][32][264]
    __half* sX = (__half*)(smem_raw + SX_OFF);   // [2][32][136]
    uint32_t mb0 = sbase;           // mbar[0]
    uint32_t mb1 = sbase + 8;       // mbar[1]

    if (tid == 0) { MBAR_INIT(mb0, 1); MBAR_INIT(mb1, 1); }
    __syncthreads();

    // ---- cluster 0: attention weight precompose (before its recurrence) ----
    if (gid == 0) {
        float (*tA)[68] = (float(*)[68])(smem_raw + SX_OFF);
        float (*tB)[68] = (float(*)[68])(smem_raw + SX_OFF + 4352);
        float* svc = (float*)(smem_raw + SX_OFF + 8704);
        const float* Wq   = in_proj_W;
        const float* WkWv = in_proj_W + EDIM * EDIM;
        for (int tix = rank; tix < 40; tix += 8) {
            int tm = tix >> 2, tn = tix & 3;
            int mg = tm * 64;
            float* Crow = (mg < EDIM) ? (Mkp + (size_t)mg * HID)
                                      : (MA1 + (size_t)(mg - EDIM) * HID);
            tile64(WkWv + (size_t)mg * EDIM, EDIM, false,
                   proj_W + tn * 64, HID, Crow + tn * 64, HID, EDIM, tid, tA, tB);
        }
        __threadfence();
        CLUSTER_SYNC();
        for (int tix = rank; tix < 40; tix += 8) {
            if (tix < 20) {
                int tm = tix >> 2, tn = tix & 3;
                tile64(out_proj_W + (size_t)tm * 64 * EDIM, EDIM, false,
                       MA1 + tn * 64, HID,
                       Amat + (size_t)tm * 64 * HID + tn * 64, HID, EDIM, tid, tA, tB);
            } else {
                int u = tix - 20;
                int tm = u >> 2, tn = u & 3;
                tile64(Wq + tm * 64, EDIM, true,
                       Mkp + tn * 64, HID,
                       P + (size_t)tm * 64 * HID + tn * 64, HID, EDIM, tid, tA, tB);
            }
        }
        if (rank == 0 && tid < HID) {
            float a = 0.f;
            for (int e = 0; e < EDIM; e++) a += in_proj_b[e] * Mkp[(size_t)e * HID + tid];
            cqk[tid] = a;
        }
        if (rank == 1) {
            for (int e = tid; e < EDIM; e += 256) {
                float a = in_proj_b[2 * EDIM + e];
                const float* wr = in_proj_W + (size_t)(2 * EDIM + e) * EDIM;
                for (int k = 0; k < EDIM; k++) a += wr[k] * proj_b[k];
                svc[e] = a;
            }
            __syncthreads();
            for (int e = tid; e < EDIM; e += 256) {
                float a = out_proj_b[e];
                const float* wr = out_proj_W + (size_t)e * EDIM;
                for (int k = 0; k < EDIM; k++) a += wr[k] * svc[k];
                aconst[e] = a;
            }
        }
        __syncthreads();
    }

    // ---- cluster barrier: mbarrier init visible before any st.async ----
    CLUSTER_SYNC();

    // ---- weight fragment preload (permuted gather, fp16) ----
    int wid = tid >> 5, lane = tid & 31;
    int g = lane >> 2, t4 = lane & 3;
    int warp_n = wid * 16;
    int odd = lane & 1;
    int b2 = (lane >> 1) & 1;

    uint32_t bregh[2][16][2];
    uint32_t bregx[2][8][2];
    #pragma unroll
    for (int j = 0; j < 2; j++) {
        int col = n0 + warp_n + 8 * j + g;          // permuted row (4u+gate)
        int o = (col & 3) * HID + (col >> 2);       // original row
        const float* wrow = W_hh + (size_t)o * HID;
        #pragma unroll
        for (int kk = 0; kk < 16; kk++) {
            bregh[j][kk][0] = pack_h2(__ldg(wrow + kk * 16 + 2 * t4),
                                      __ldg(wrow + kk * 16 + 2 * t4 + 1));
            bregh[j][kk][1] = pack_h2(__ldg(wrow + kk * 16 + 2 * t4 + 8),
                                      __ldg(wrow + kk * 16 + 2 * t4 + 9));
        }
        const float* xrow = W_ih + (size_t)o * DIN;
        #pragma unroll
        for (int kk = 0; kk < 8; kk++) {
            bregx[j][kk][0] = pack_h2(__ldg(xrow + kk * 16 + 2 * t4),
                                      __ldg(xrow + kk * 16 + 2 * t4 + 1));
            bregx[j][kk][1] = pack_h2(__ldg(xrow + kk * 16 + 2 * t4 + 8),
                                      __ldg(xrow + kk * 16 + 2 * t4 + 9));
        }
    }
    float creg[4] = {0.f, 0.f, 0.f, 0.f};

    // epilogue coords: rows (local) and unit pair base
    int rloc[2];
    rloc[0] = g + (odd ? 8 : 0);
    rloc[1] = rloc[0] + 16;
    int ubase = (n0 + warp_n) >> 2;
    int eu = ubase + b2;            // gate-accumulator unit (pre-exchange)
    int unit2 = ubase + 2 * b2;     // adjacent-unit pair base (post-exchange)
    float4 bb[2];
    #pragma unroll
    for (int j = 0; j < 2; j++) {
        int u = eu + 2 * j;
        bb[j].x = __ldg(b_ih + u)           + __ldg(b_hh + u);
        bb[j].y = __ldg(b_ih + HID + u)     + __ldg(b_hh + HID + u);
        bb[j].z = __ldg(b_ih + 2 * HID + u) + __ldg(b_hh + 2 * HID + u);
        bb[j].w = __ldg(b_ih + 3 * HID + u) + __ldg(b_hh + 3 * HID + u);
    }

    // peer smem bases
    uint32_t peer[8];
    #pragma unroll
    for (int r = 0; r < 8; r++) peer[r] = mapa_u32(sbase, r);

    // preload x tile for t=0 into sX buf 0
    #pragma unroll
    for (int itr = 0; itr < 4; itr++) {
        int gi = itr * 256 + tid;
        int row = gi >> 5;
        int c4 = gi & 31;
        float4 v = __ldg((const float4*)(X + ((size_t)(m0 + row) * TSEQ + 0) * DIN + c4 * 4));
        uint2 pk = { pack_h2(v.x, v.y), pack_h2(v.z, v.w) };
        *(uint2*)&sX[row * 136 + c4 * 4] = pk;
    }
    __syncthreads();

    int ph[2] = {0, 0};
    // precomputed DSMEM byte offsets for my (row, unit2) pairs, per buffer
    uint32_t hoff[2][2];
    #pragma unroll
    for (int b = 0; b < 2; b++)
        #pragma unroll
        for (int i = 0; i < 2; i++)
            hoff[b][i] = SH_OFF + (uint32_t)((b * 32 + rloc[i]) * 264 + unit2) * 2;

    for (int t = 0; t < TSEQ; t++) {
        int cb = t & 1, nb = cb ^ 1;
        uint32_t mb_cb = sbase + 8u * cb;
        if (tid == 0 && t + 1 < TSEQ) MBAR_EXPECT_TX(sbase + 8u * nb, 16384);
        if (t > 0) { MBAR_WAIT(mb_cb, ph[cb]); ph[cb] ^= 1; }
        __syncthreads();

        // issue x_{t+1} loads into sX[nb] (overlaps mma)
        if (t + 1 < TSEQ) {
            #pragma unroll
            for (int itr = 0; itr < 4; itr++) {
                int gi = itr * 256 + tid;
                int row = gi >> 5;
                int c4 = gi & 31;
                float4 v = __ldg((const float4*)(X + ((size_t)(m0 + row) * TSEQ + (t + 1)) * DIN + c4 * 4));
                uint2 pk = { pack_h2(v.x, v.y), pack_h2(v.z, v.w) };
                *(uint2*)&sX[(nb * 32 + row) * 136 + c4 * 4] = pk;
            }
        }

        float c[2][2][4];
        #pragma unroll
        for (int i = 0; i < 2; i++)
            #pragma unroll
            for (int j = 0; j < 2; j++)
                #pragma unroll
                for (int e = 0; e < 4; e++) c[i][j][e] = 0.f;

        if (t > 0) {
            const __half* sHc = sH + (size_t)cb * 32 * 264;
            #pragma unroll
            for (int kk = 0; kk < 16; kk++) {
                #pragma unroll
                for (int i = 0; i < 2; i++) {
                    int r0 = 16 * i + g;
                    const __half* alo = &sHc[r0 * 264 + kk * 16 + 2 * t4];
                    const __half* ahi = &sHc[(r0 + 8) * 264 + kk * 16 + 2 * t4];
                    uint32_t a0 = *(const uint32_t*)alo;
                    uint32_t a2 = *(const uint32_t*)(alo + 8);
                    uint32_t a1 = *(const uint32_t*)ahi;
                    uint32_t a3 = *(const uint32_t*)(ahi + 8);
                    mma_f16(c[i][0], a0, a1, a2, a3, bregh[0][kk][0], bregh[0][kk][1]);
                    mma_f16(c[i][1], a0, a1, a2, a3, bregh[1][kk][0], bregh[1][kk][1]);
                }
            }
        }
        {
            const __half* sXc = sX + (size_t)cb * 32 * 136;
            #pragma unroll
            for (int kk = 0; kk < 8; kk++) {
                #pragma unroll
                for (int i = 0; i < 2; i++) {
                    int r0 = 16 * i + g;
                    const __half* alo = &sXc[r0 * 136 + kk * 16 + 2 * t4];
                    const __half* ahi = &sXc[(r0 + 8) * 136 + kk * 16 + 2 * t4];
                    uint32_t a0 = *(const uint32_t*)alo;
                    uint32_t a2 = *(const uint32_t*)(alo + 8);
                    uint32_t a1 = *(const uint32_t*)ahi;
                    uint32_t a3 = *(const uint32_t*)(ahi + 8);
                    mma_f16(c[i][0], a0, a1, a2, a3, bregx[0][kk][0], bregx[0][kk][1]);
                    mma_f16(c[i][1], a0, a1, a2, a3, bregx[1][kk][0], bregx[1][kk][1]);
                }
            }
        }

        // ---- epilogue: gates, cell, pack adjacent-unit pairs ----
        float hv[2][2];
        #pragma unroll
        for (int i = 0; i < 2; i++) {
            #pragma unroll
            for (int j = 0; j < 2; j++) {
                float u0 = odd ? c[i][j][0] : c[i][j][2];
                float u1 = odd ? c[i][j][1] : c[i][j][3];
                float rx0 = __shfl_xor_sync(0xffffffffu, u0, 1);
                float rx1 = __shfl_xor_sync(0xffffffffu, u1, 1);
                float gi, gf, gg, go;
                if (!odd) { gi = c[i][j][0]; gf = c[i][j][1]; gg = rx0; go = rx1; }
                else      { gi = rx0; gf = rx1; gg = c[i][j][2]; go = c[i][j][3]; }
                gi += bb[j].x; gf += bb[j].y; gg += bb[j].z; go += bb[j].w;
                float i_ = fsig(gi);
                float f_ = fsig(gf);
                float g_ = ftanh(gg);
                float o_ = fsig(go);
                int ci = i * 2 + j;
                float cn = f_ * creg[ci] + i_ * g_;
                creg[ci] = cn;
                hv[i][j] = o_ * ftanh(cn);
            }
        }
        // exchange across lane^2 so each thread holds units {unit2, unit2+1}
        uint32_t pkr[2];
        #pragma unroll
        for (int i = 0; i < 2; i++) {
            float send = b2 ? hv[i][0] : hv[i][1];
            float recv = __shfl_xor_sync(0xffffffffu, send, 2);
            pkr[i] = b2 ? pack_h2(recv, hv[i][1]) : pack_h2(hv[i][0], recv);
        }

        // broadcast h to all 8 cluster peers (incl. self) via st.async
        if (t + 1 < TSEQ) {
            #pragma unroll
            for (int r = 0; r < 8; r++) {
                uint32_t pb = peer[r];
                uint32_t pm = pb + 8u * nb;
                st_async_b32(pb + hoff[nb][0], pkr[0], pm);
                st_async_b32(pb + hoff[nb][1], pkr[1], pm);
            }
        }
        // archive hs (packed)
        #pragma unroll
        for (int i = 0; i < 2; i++)
            *(__half2*)(hs + ((size_t)(m0 + rloc[i]) * TSEQ + t) * HID + unit2) =
                *reinterpret_cast<__half2*>(&pkr[i]);
    }

    // no CTA may exit while peers could still target its smem
    CLUSTER_SYNC();
}

// ---------------- medium GEMM with register double-buffering --------------------------
template <bool TRANS, bool RELU>
__global__ __launch_bounds__(256) void gemm_med(
    const float* __restrict__ A, const float* __restrict__ W,
    const float* __restrict__ bias, float* __restrict__ C,
    int M, int N, int K, int lda, int ldw, int ldc) {
    __shared__ float sA[16][68];
    __shared__ float sW[16][68];
    int m0 = blockIdx.y * 64, n0 = blockIdx.x * 64;
    int tid = threadIdx.x;
    int tx = tid & 15, ty = tid >> 4;
    float acc[4][4] = {};
    float pa[4], pw[4];

    #pragma unroll
    for (int i = 0; i < 4; i++) {
        int idx = tid + i * 256;
        int r = idx >> 4, k = idx & 15;
        int mm = m0 + r, kk = k;
        pa[i] = (mm < M && kk < K) ? A[(size_t)mm * lda + kk] : 0.f;
        int nn = n0 + r;
        float v = 0.f;
        if (TRANS) { if (kk < K && nn < N) v = W[(size_t)kk * ldw + nn]; }
        else       { if (nn < N && kk < K) v = W[(size_t)nn * ldw + kk]; }
        pw[i] = v;
    }
    for (int k0 = 0; k0 < K; k0 += 16) {
        #pragma unroll
        for (int i = 0; i < 4; i++) {
            int idx = tid + i * 256;
            int r = idx >> 4, k = idx & 15;
            sA[k][r] = pa[i];
            sW[k][r] = pw[i];
        }
        __syncthreads();
        if (k0 + 16 < K) {
            #pragma unroll
            for (int i = 0; i < 4; i++) {
                int idx = tid + i * 256;
                int r = idx >> 4, k = idx & 15;
                int mm = m0 + r, kk = k0 + 16 + k;
                pa[i] = (mm < M && kk < K) ? A[(size_t)mm * lda + kk] : 0.f;
                int nn = n0 + r;
                float v = 0.f;
                if (TRANS) { if (kk < K && nn < N) v = W[(size_t)kk * ldw + nn]; }
                else       { if (nn < N && kk < K) v = W[(size_t)nn * ldw + kk]; }
                pw[i] = v;
            }
        }
        #pragma unroll
        for (int k = 0; k < 16; k++) {
            float4 a = *(const float4*)&sA[k][ty * 4];
            float4 b = *(const float4*)&sW[k][tx * 4];
            acc[0][0] += a.x * b.x; acc[0][1] += a.x * b.y; acc[0][2] += a.x * b.z; acc[0][3] += a.x * b.w;
            acc[1][0] += a.y * b.x; acc[1][1] += a.y * b.y; acc[1][2] += a.y * b.z; acc[1][3] += a.y * b.w;
            acc[2][0] += a.z * b.x; acc[2][1] += a.z * b.y; acc[2][2] += a.z * b.z; acc[2][3] += a.z * b.w;
            acc[3][0] += a.w * b.x; acc[3][1] += a.w * b.y; acc[3][2] += a.w * b.z; acc[3][3] += a.w * b.w;
        }
        __syncthreads();
    }
    #pragma unroll
    for (int r = 0; r < 4; r++) {
        int m = m0 + ty * 4 + r;
        if (m >= M) continue;
        #pragma unroll
        for (int cc = 0; cc < 4; cc++) {
            int n = n0 + tx * 4 + cc;
            if (n >= N) continue;
            float v = acc[r][cc];
            if (bias) v += bias[n];
            if (RELU) v = fmaxf(v, 0.f);
            C[(size_t)m * ldc + n] = v;
        }
    }
}

// ---------------- fused attention over fp16 hs (512 threads) -------------------------
__global__ __launch_bounds__(512) void attn_kernel(
    const __half* __restrict__ hs, const float* __restrict__ qk,
    float* __restrict__ hbar) {
    int b = blockIdx.x;
    __shared__ float sc[TSEQ];
    __shared__ float red[256];
    __shared__ float sqk[HID];
    __shared__ float part[2][256];
    int tid = threadIdx.x;
    int lane = tid & 31, w = tid >> 5;
    if (tid < HID) sqk[tid] = qk[b * HID + tid];
    __syncthreads();
    for (int t = w; t < TSEQ; t += 16) {
        const __half2* hrow = (const __half2*)(hs + ((size_t)b * TSEQ + t) * HID);
        float p = 0.f;
        #pragma unroll
        for (int j = 0; j < 4; j++) {
            int h2i = lane + 32 * j;
            float2 hv = __half22float2(hrow[h2i]);
            p += hv.x * sqk[2 * h2i] + hv.y * sqk[2 * h2i + 1];
        }
        #pragma unroll
        for (int o = 16; o > 0; o >>= 1) p += __shfl_down_sync(0xffffffffu, p, o);
        if (lane == 0) sc[t] = p;
    }
    __syncthreads();
    float scale = 1.0f / sqrtf((float)EDIM);
    float v = (tid < 256) ? sc[tid] * scale : -1e30f;
    if (tid < 256) red[tid] = v;
    __syncthreads();
    for (int s = 128; s > 0; s >>= 1) { if (tid < s) red[tid] = fmaxf(red[tid], red[tid + s]); __syncthreads(); }
    float mx = red[0]; __syncthreads();
    float ev = (tid < 256) ? __expf(v - mx) : 0.f;
    if (tid < 256) red[tid] = ev;
    __syncthreads();
    for (int s = 128; s > 0; s >>= 1) { if (tid < s) red[tid] += red[tid + s]; __syncthreads(); }
    float sum = red[0]; __syncthreads();
    if (tid < 256) sc[tid] = __fdividef(ev, sum);
    __syncthreads();
    int h = tid & 255, half = tid >> 8;
    const __half* hb = hs + (size_t)b * TSEQ * HID;
    float acc = 0.f;
    for (int t = half * 128; t < (half + 1) * 128; t++)
        acc += sc[t] * __half2float(hb[(size_t)t * HID + h]);
    part[half][h] = acc;
    __syncthreads();
    if (tid < 256) hbar[b * HID + tid] = part[0][tid] + part[1][tid];
}

// ---------------- concat helpers ----------------
__global__ void sf_build(const __half* __restrict__ hs, const float* __restrict__ s,
                         float* __restrict__ sf) {
    int idx = blockIdx.x * blockDim.x + threadIdx.x;
    if (idx >= BATCH * EDIM) return;
    int b = idx / EDIM, j = idx % EDIM;
    sf[idx] = (j < HID) ? __half2float(hs[((size_t)b * TSEQ + (TSEQ - 1)) * HID + j])
                        : s[b * FDIM + (j - HID)];
}
__global__ void scopy(const float* __restrict__ s, float* __restrict__ merged) {
    int idx = blockIdx.x * blockDim.x + threadIdx.x;
    if (idx >= BATCH * FDIM) return;
    int b = idx >> 6, f = idx & 63;
    merged[(size_t)b * NMERG + EDIM + f] = s[idx];
}

// ---------------- 10-qubit VQC ----------------
struct c2f { float x, y; };
__device__ __forceinline__ c2f cmul(c2f a, c2f b) { return { a.x * b.x - a.y * b.y, a.x * b.y + a.y * b.x }; }
__device__ __forceinline__ c2f cadd(c2f a, c2f b) { return { a.x + b.x, a.y + b.y }; }
__device__ __forceinline__ void matmul2(c2f C[2][2], const c2f A[2][2], const c2f B[2][2]) {
    #pragma unroll
    for (int i = 0; i < 2; i++)
        #pragma unroll
        for (int j = 0; j < 2; j++)
            C[i][j] = cadd(cmul(A[i][0], B[0][j]), cmul(A[i][1], B[1][j]));
}
__device__ __forceinline__ int cnot_ring_gather(int i) {
    int j = i;
    j ^= (j & 1) << 9;
    #pragma unroll
    for (int k = 9; k >= 1; k--)
        j ^= ((j >> (10 - k)) & 1) << (9 - k);
    return j;
}

__global__ __launch_bounds__(512) void vqc_kernel(float* __restrict__ merged,
                                                  const float* __restrict__ qw) {
    int b = blockIdx.x;
    __shared__ c2f psi[1024];
    __shared__ float sang[40];
    __shared__ float wsum[16][10];
    int tid = threadIdx.x;
    int lane = tid & 31, w = tid >> 5;
    const float PI_F = 3.14159265358979323846f;
    psi[tid] = { 0.03125f, 0.f };
    psi[tid + 512] = { 0.03125f, 0.f };
    if (tid < 40) sang[tid] = ftanh(merged[(size_t)b * NMERG + tid]) * PI_F;
    __syncthreads();

    int gidx0 = cnot_ring_gather(tid);
    int gidx1 = cnot_ring_gather(tid + 512);

    for (int layer = 0; layer < 4; layer++) {
        for (int q = 0; q < 10; q++) {
            int idx = layer * 10 + q;
            float a = sang[idx];
            float w0 = qw[idx * 3 + 0], w1 = qw[idx * 3 + 1], w2 = qw[idx * 3 + 2];
            float ch, sh; __sincosf(0.5f * a, &sh, &ch);
            c2f Rx[2][2] = { { {ch, 0.f}, {0.f, -sh} }, { {0.f, -sh}, {ch, 0.f} } };
            c2f Rya[2][2] = { { {ch, 0.f}, {-sh, 0.f} }, { {sh, 0.f}, {ch, 0.f} } };
            c2f T1[2][2]; matmul2(T1, Rya, Rx);
            float c0, s0; __sincosf(0.5f * w0, &s0, &c0);
            c2f Rz0[2][2] = { { {c0, -s0}, {0.f, 0.f} }, { {0.f, 0.f}, {c0, s0} } };
            c2f T2[2][2]; matmul2(T2, Rz0, T1);
            float c1, s1; __sincosf(0.5f * w1, &s1, &c1);
            c2f Ry1[2][2] = { { {c1, 0.f}, {-s1, 0.f} }, { {s1, 0.f}, {c1, 0.f} } };
            c2f T3[2][2]; matmul2(T3, Ry1, T2);
            float c2r, s2r; __sincosf(0.5f * w2, &s2r, &c2r);
            c2f Rz2[2][2] = { { {c2r, -s2r}, {0.f, 0.f} }, { {0.f, 0.f}, {c2r, s2r} } };
            c2f U[2][2]; matmul2(U, Rz2, T3);

            int bq = 9 - q;
            int low = tid & ((1 << bq) - 1);
            int i0 = ((tid >> bq) << (bq + 1)) | low;
            int i1 = i0 | (1 << bq);
            __syncthreads();
            c2f a0 = psi[i0], a1 = psi[i1];
            psi[i0] = cadd(cmul(U[0][0], a0), cmul(U[0][1], a1));
            psi[i1] = cadd(cmul(U[1][0], a0), cmul(U[1][1], a1));
        }
        __syncthreads();
        c2f v0 = psi[gidx0], v1 = psi[gidx1];
        __syncthreads();
        psi[tid] = v0;
        psi[tid + 512] = v1;
    }
    __syncthreads();
    c2f p0 = psi[tid], p1 = psi[tid + 512];
    float n0 = p0.x * p0.x + p0.y * p0.y;
    float n1 = p1.x * p1.x + p1.y * p1.y;
    float acc[10];
    #pragma unroll
    for (int k = 0; k < 10; k++) {
        int bp_ = 9 - k;
        float s0v = ((tid >> bp_) & 1) ? -n0 : n0;
        float s1v = (((tid + 512) >> bp_) & 1) ? -n1 : n1;
        acc[k] = s0v + s1v;
        #pragma unroll
        for (int o = 16; o > 0; o >>= 1) acc[k] += __shfl_down_sync(0xffffffffu, acc[k], o);
    }
    if (lane == 0)
        #pragma unroll
        for (int k = 0; k < 10; k++) wsum[w][k] = acc[k];
    __syncthreads();
    if (tid < 10) {
        float a = 0.f;
        #pragma unroll
        for (int ww = 0; ww < 16; ww++) a += wsum[ww][tid];
        merged[(size_t)b * NMERG + DM + tid] = a;
    }
}

// ---------------- host launch ----------------
#define GETSYM(p, sym) do { void* _t = nullptr; cudaGetSymbolAddress(&_t, sym); (p) = (float*)_t; } while (0)

extern "C" void kernel_launch(void* const* d_in, const int* in_sizes, int n_in,
                              void* d_out, int out_size) {
    const float* s          = (const float*)d_in[0];
    const float* lstm_s     = (const float*)d_in[1];
    const float* W_ih       = (const float*)d_in[2];
    const float* W_hh       = (const float*)d_in[3];
    const float* b_ih       = (const float*)d_in[4];
    const float* b_hh       = (const float*)d_in[5];
    const float* proj_W     = (const float*)d_in[6];
    const float* proj_b     = (const float*)d_in[7];
    const float* in_proj_W  = (const float*)d_in[8];
    const float* in_proj_b  = (const float*)d_in[9];
    const float* out_proj_W = (const float*)d_in[10];
    const float* out_proj_b = (const float*)d_in[11];
    const float* qweights   = (const float*)d_in[12];
    const float* W1         = (const float*)d_in[13];
    const float* b1         = (const float*)d_in[14];
    const float* W2         = (const float*)d_in[15];
    const float* b2         = (const float*)d_in[16];
    float* out = (float*)d_out;

    float *sf, *qk, *Mkp, *MA1, *Amat, *P, *cqk, *aconst, *hbar, *merged, *x1;
    __half* hs;
    { void* _t = nullptr; cudaGetSymbolAddress(&_t, d_hs); hs = (__half*)_t; }
    GETSYM(sf, d_sf);
    GETSYM(qk, d_qk);   GETSYM(Mkp, d_Mkp); GETSYM(MA1, d_MA1);
    GETSYM(Amat, d_Amat); GETSYM(P, d_P);   GETSYM(cqk, d_cqk);
    GETSYM(aconst, d_aconst);
    GETSYM(hbar, d_hbar);
    GETSYM(merged, d_merged); GETSYM(x1, d_x1);

    // merged[:, EDIM:DM] = s (input-only dependency)
    scopy<<<(BATCH * FDIM + 255) / 256, 256>>>(s, merged);

    // persistent fused LSTM (DSMEM cluster h-exchange) + cluster-0 precompose
    cudaFuncSetAttribute(lstm_persist, cudaFuncAttributeMaxDynamicSharedMemorySize, SMEM_TOTAL);
    lstm_persist<<<NBLK, 256, SMEM_TOTAL>>>(lstm_s, W_ih, W_hh, b_ih, b_hh, hs,
                                            in_proj_W, in_proj_b, proj_W, proj_b,
                                            out_proj_W, out_proj_b,
                                            Mkp, MA1, Amat, P, cqk, aconst);

    // state_full = [h_last, s]; qk = sf @ P + cqk
    sf_build<<<(BATCH * EDIM + 255) / 256, 256>>>(hs, s, sf);
    gemm_med<true, false><<<dim3(4, 8), 256>>>(sf, P, cqk, qk, BATCH, HID, EDIM, EDIM, HID, HID);

    // fused attention over hs
    attn_kernel<<<BATCH, 512>>>(hs, qk, hbar);

    // attn_out written directly into merged[:, :EDIM]
    gemm_med<false, false><<<dim3(5, 8), 256>>>(hbar, Amat, aconst, merged, BATCH, EDIM, HID, HID, HID, NMERG);

    // VQC (writes qfeat into merged[:, DM:])
    vqc_kernel<<<BATCH, 512>>>(merged, qweights);

    // MLP
    gemm_med<false, true><<<dim3(8, 8), 256>>>(merged, W1, b1, x1, BATCH, NL1, NMERG, NMERG, NMERG, NL1);
    gemm_med<false, false><<<dim3(1, 8), 256>>>(x1, W2, b2, out, BATCH, NACT, NL1, NL1, NL1, NACT);
}

// round 15
// speedup vs baseline: 2.0285x; 2.0285x over previous
#include <cuda_runtime.h>
#include <cuda_fp16.h>
#include <math.h>
#include <stdint.h>

#define BATCH 512
#define TSEQ  256
#define DIN   128
#define HID   256
#define G4    1024
#define FDIM  64
#define EDIM  320
#define DM    384
#define NMERG 394
#define NL1   512
#define NACT  8

#define NBLK   128   // lstm blocks: 16 batch-groups x 8 col-tiles
#define NGRP   8     // blocks per batch-group barrier
#define NPRE   20    // precompose blocks riding along in lstm_persist

// ---------------- scratch (static device memory; no allocations) ----------------
__device__ __half d_hs[33554432];      // [B, T, H] fp16 hidden states
__device__ __half d_hbuf[2 * BATCH * HID]; // double-buffered compact h (fp16)
__device__ int   d_bar[16 * TSEQ + 1]; // per (group, step) barriers + [last] = precompose bar
__device__ float d_sf[BATCH * EDIM];   // state_full
__device__ float d_qk[BATCH * HID];
__device__ float d_Mkp[EDIM * HID];    // Wk @ proj_W
__device__ float d_MA1[EDIM * HID];    // Wv @ proj_W
__device__ float d_Amat[EDIM * HID];   // Wo @ Wv @ proj_W
__device__ float d_P[EDIM * HID];      // Wq^T @ Mkp
__device__ float d_cqk[HID];           // bq @ Mkp
__device__ float d_aconst[EDIM];
__device__ float d_hbar[BATCH * HID];
__device__ float d_merged[BATCH * NMERG];  // [attn_out | s | qfeat]
__device__ float d_x1[BATCH * NL1];

// ---------------- helpers ----------------
__device__ __forceinline__ uint32_t pack_h2(float x, float y) {
    __half2 t = __floats2half2_rn(x, y);
    return *reinterpret_cast<uint32_t*>(&t);
}
__device__ __forceinline__ void mma_f16(float* c, uint32_t a0, uint32_t a1,
                                        uint32_t a2, uint32_t a3,
                                        uint32_t b0, uint32_t b1) {
    asm volatile("mma.sync.aligned.m16n8k16.row.col.f32.f16.f16.f32 "
        "{%0,%1,%2,%3}, {%4,%5,%6,%7}, {%8,%9}, {%0,%1,%2,%3};"
        : "+f"(c[0]), "+f"(c[1]), "+f"(c[2]), "+f"(c[3])
        : "r"(a0), "r"(a1), "r"(a2), "r"(a3), "r"(b0), "r"(b1));
}
__device__ __forceinline__ float fsig(float x) {
    return __fdividef(1.f, 1.f + __expf(-x));
}
__device__ __forceinline__ float ftanh(float x) {
    return 2.f * fsig(2.f * x) - 1.f;
}
// release-ordered arrive (orders all prior global stores) and acquire poll
__device__ __forceinline__ void bar_arrive_release(int* p) {
    asm volatile("red.release.gpu.global.add.s32 [%0], 1;" :: "l"(p) : "memory");
}
__device__ __forceinline__ int bar_poll_acquire(const int* p) {
    int v;
    asm volatile("ld.acquire.gpu.global.s32 %0, [%1];" : "=r"(v) : "l"(p) : "memory");
    return v;
}

// ---------------- 64x64 fp32 tile GEMM (device; used by precompose blocks) -----------
__device__ void tile64(const float* __restrict__ A, int lda, bool transA,
                       const float* __restrict__ B, int ldb,
                       float* __restrict__ C, int ldc, int K, int tid,
                       float (*sA)[68], float (*sW)[68]) {
    int tx = tid & 15, ty = tid >> 4;
    float acc[4][4] = {};
    for (int k0 = 0; k0 < K; k0 += 16) {
        #pragma unroll
        for (int i = 0; i < 4; i++) {
            int idx = tid + i * 256;
            int r = idx >> 4, k = idx & 15;
            sA[k][r] = transA ? A[(size_t)(k0 + k) * lda + r]
                              : A[(size_t)r * lda + k0 + k];
            sW[k][r] = B[(size_t)(k0 + k) * ldb + r];
        }
        __syncthreads();
        #pragma unroll
        for (int k = 0; k < 16; k++) {
            float4 a = *(const float4*)&sA[k][ty * 4];
            float4 b = *(const float4*)&sW[k][tx * 4];
            acc[0][0] += a.x * b.x; acc[0][1] += a.x * b.y; acc[0][2] += a.x * b.z; acc[0][3] += a.x * b.w;
            acc[1][0] += a.y * b.x; acc[1][1] += a.y * b.y; acc[1][2] += a.y * b.z; acc[1][3] += a.y * b.w;
            acc[2][0] += a.z * b.x; acc[2][1] += a.z * b.y; acc[2][2] += a.z * b.z; acc[2][3] += a.z * b.w;
            acc[3][0] += a.w * b.x; acc[3][1] += a.w * b.y; acc[3][2] += a.w * b.z; acc[3][3] += a.w * b.w;
        }
        __syncthreads();
    }
    #pragma unroll
    for (int r = 0; r < 4; r++)
        #pragma unroll
        for (int cc = 0; cc < 4; cc++)
            C[(size_t)(ty * 4 + r) * ldc + tx * 4 + cc] = acc[r][cc];
}

// ---------------- persistent fused LSTM + hidden weight precompose -------------------
__global__ __launch_bounds__(256, 1) void lstm_persist(
    const float* __restrict__ X, const float* __restrict__ W_ih,
    const float* __restrict__ W_hh, const float* __restrict__ b_ih,
    const float* __restrict__ b_hh,
    __half* __restrict__ hs, __half* __restrict__ hbuf, int* __restrict__ bar,
    const float* __restrict__ in_proj_W, const float* __restrict__ in_proj_b,
    const float* __restrict__ proj_W, const float* __restrict__ proj_b,
    const float* __restrict__ out_proj_W, const float* __restrict__ out_proj_b,
    float* __restrict__ Mkp, float* __restrict__ MA1, float* __restrict__ Amat,
    float* __restrict__ P, float* __restrict__ cqk, float* __restrict__ aconst)
{
    __shared__ __half sA[32][264];   // h tile
    __shared__ __half sX[32][136];   // x tile
    __shared__ float tA[16][68];     // precompose tiles
    __shared__ float tB[16][68];
    __shared__ float svc[EDIM];
    int tid = threadIdx.x;

    // ===================== precompose blocks =====================
    if (blockIdx.x >= NBLK) {
        int p = blockIdx.x - NBLK;   // 0..19
        const float* Wq   = in_proj_W;
        const float* WkWv = in_proj_W + EDIM * EDIM;   // [Wk; Wv], 640 x 320
        for (int tix = p; tix < 40; tix += NPRE) {
            int tm = tix >> 2, tn = tix & 3;
            int mg = tm * 64;
            float* Crow = (mg < EDIM) ? (Mkp + (size_t)mg * HID)
                                      : (MA1 + (size_t)(mg - EDIM) * HID);
            tile64(WkWv + (size_t)mg * EDIM, EDIM, false,
                   proj_W + tn * 64, HID,
                   Crow + tn * 64, HID, EDIM, tid, tA, tB);
        }
        __syncthreads();
        if (tid == 0) {
            bar_arrive_release(bar + 16 * TSEQ);
            while (bar_poll_acquire(bar + 16 * TSEQ) < NPRE) {}
        }
        __syncthreads();
        {
            int tm = p >> 2, tn = p & 3;
            tile64(out_proj_W + (size_t)tm * 64 * EDIM, EDIM, false,
                   MA1 + tn * 64, HID,
                   Amat + (size_t)tm * 64 * HID + tn * 64, HID, EDIM, tid, tA, tB);
            tile64(Wq + tm * 64, EDIM, true,
                   Mkp + tn * 64, HID,
                   P + (size_t)tm * 64 * HID + tn * 64, HID, EDIM, tid, tA, tB);
        }
        if (p == 0) {
            if (tid < HID) {
                float a = 0.f;
                for (int e = 0; e < EDIM; e++) a += in_proj_b[e] * Mkp[(size_t)e * HID + tid];
                cqk[tid] = a;
            }
        }
        if (p == 1) {
            for (int e = tid; e < EDIM; e += 256) {
                float a = in_proj_b[2 * EDIM + e];
                const float* wr = in_proj_W + (size_t)(2 * EDIM + e) * EDIM;
                for (int k = 0; k < EDIM; k++) a += wr[k] * proj_b[k];
                svc[e] = a;
            }
            __syncthreads();
            for (int e = tid; e < EDIM; e += 256) {
                float a = out_proj_b[e];
                const float* wr = out_proj_W + (size_t)e * EDIM;
                for (int k = 0; k < EDIM; k++) a += wr[k] * svc[k];
                aconst[e] = a;
            }
        }
        return;
    }

    // ===================== LSTM blocks =====================
    int bx = blockIdx.x & 7;        // col tile (128 cols)
    int gid = blockIdx.x >> 3;      // batch group (0..15, 32 rows)
    int n0 = bx * 128, m0 = gid * 32;
    int wid = tid >> 5, lane = tid & 31;
    int g = lane >> 2, t4 = lane & 3;
    int warp_n = wid * 16;
    int odd = lane & 1;
    int b2 = (lane >> 1) & 1;

    uint32_t bregh[2][16][2];
    uint32_t bregx[2][8][2];
    #pragma unroll
    for (int j = 0; j < 2; j++) {
        int col = n0 + warp_n + 8 * j + g;          // permuted row (4u+gate)
        int o = (col & 3) * HID + (col >> 2);       // original row
        const float* wrow = W_hh + (size_t)o * HID;
        #pragma unroll
        for (int kk = 0; kk < 16; kk++) {
            bregh[j][kk][0] = pack_h2(__ldg(wrow + kk * 16 + 2 * t4),
                                      __ldg(wrow + kk * 16 + 2 * t4 + 1));
            bregh[j][kk][1] = pack_h2(__ldg(wrow + kk * 16 + 2 * t4 + 8),
                                      __ldg(wrow + kk * 16 + 2 * t4 + 9));
        }
        const float* xrow = W_ih + (size_t)o * DIN;
        #pragma unroll
        for (int kk = 0; kk < 8; kk++) {
            bregx[j][kk][0] = pack_h2(__ldg(xrow + kk * 16 + 2 * t4),
                                      __ldg(xrow + kk * 16 + 2 * t4 + 1));
            bregx[j][kk][1] = pack_h2(__ldg(xrow + kk * 16 + 2 * t4 + 8),
                                      __ldg(xrow + kk * 16 + 2 * t4 + 9));
        }
    }
    float creg[4] = {0.f, 0.f, 0.f, 0.f};

    // epilogue coords
    int erow[2];
    erow[0] = m0 + g + (odd ? 8 : 0);
    erow[1] = erow[0] + 16;
    int ubase = (n0 + warp_n) >> 2;
    int eu = ubase + b2;            // gate-accumulator unit (pre-exchange)
    int unit2 = ubase + 2 * b2;     // adjacent-unit pair base (post-exchange)
    float4 bb[2];
    #pragma unroll
    for (int j = 0; j < 2; j++) {
        int u = eu + 2 * j;
        bb[j].x = __ldg(b_ih + u)           + __ldg(b_hh + u);
        bb[j].y = __ldg(b_ih + HID + u)     + __ldg(b_hh + HID + u);
        bb[j].z = __ldg(b_ih + 2 * HID + u) + __ldg(b_hh + 2 * HID + u);
        bb[j].w = __ldg(b_ih + 3 * HID + u) + __ldg(b_hh + 3 * HID + u);
    }

    // preload x tile for t=0
    #pragma unroll
    for (int itr = 0; itr < 4; itr++) {
        int gi = itr * 256 + tid;
        int row = gi >> 5;
        int c4 = gi & 31;
        float4 v = __ldg((const float4*)(X + ((size_t)(m0 + row) * TSEQ + 0) * DIN + c4 * 4));
        uint2 pk = { pack_h2(v.x, v.y), pack_h2(v.z, v.w) };
        *(uint2*)&sX[row][c4 * 4] = pk;
    }
    __syncthreads();

    for (int t = 0; t < TSEQ; t++) {
        float c[2][2][4];
        #pragma unroll
        for (int i = 0; i < 2; i++)
            #pragma unroll
            for (int j = 0; j < 2; j++)
                #pragma unroll
                for (int e = 0; e < 4; e++) c[i][j][e] = 0.f;

        if (t > 0) {
            const __half* hp = hbuf + (size_t)(t & 1) * (BATCH * HID);
            #pragma unroll
            for (int itr = 0; itr < 4; itr++) {
                int gi = itr * 256 + tid;
                int row = gi >> 5;
                int s2 = gi & 31;
                uint4 v = __ldcg((const uint4*)(hp + (size_t)(m0 + row) * HID + s2 * 8));
                *(uint4*)&sA[row][s2 * 8] = v;
            }
            __syncthreads();
            #pragma unroll
            for (int kk = 0; kk < 16; kk++) {
                #pragma unroll
                for (int i = 0; i < 2; i++) {
                    int r0 = 16 * i + g;
                    const __half* alo = &sA[r0][kk * 16 + 2 * t4];
                    const __half* ahi = &sA[r0 + 8][kk * 16 + 2 * t4];
                    uint32_t a0 = *(const uint32_t*)alo;
                    uint32_t a2 = *(const uint32_t*)(alo + 8);
                    uint32_t a1 = *(const uint32_t*)ahi;
                    uint32_t a3 = *(const uint32_t*)(ahi + 8);
                    mma_f16(c[i][0], a0, a1, a2, a3, bregh[0][kk][0], bregh[0][kk][1]);
                    mma_f16(c[i][1], a0, a1, a2, a3, bregh[1][kk][0], bregh[1][kk][1]);
                }
            }
        }
        #pragma unroll
        for (int kk = 0; kk < 8; kk++) {
            #pragma unroll
            for (int i = 0; i < 2; i++) {
                int r0 = 16 * i + g;
                const __half* alo = &sX[r0][kk * 16 + 2 * t4];
                const __half* ahi = &sX[r0 + 8][kk * 16 + 2 * t4];
                uint32_t a0 = *(const uint32_t*)alo;
                uint32_t a2 = *(const uint32_t*)(alo + 8);
                uint32_t a1 = *(const uint32_t*)ahi;
                uint32_t a3 = *(const uint32_t*)(ahi + 8);
                mma_f16(c[i][0], a0, a1, a2, a3, bregx[0][kk][0], bregx[0][kk][1]);
                mma_f16(c[i][1], a0, a1, a2, a3, bregx[1][kk][0], bregx[1][kk][1]);
            }
        }

        // ---- epilogue: gates, cell, pack adjacent-unit pairs ----
        __half* hn = hbuf + (size_t)((t + 1) & 1) * (BATCH * HID);
        float hv[2][2];
        #pragma unroll
        for (int i = 0; i < 2; i++) {
            #pragma unroll
            for (int j = 0; j < 2; j++) {
                float u0 = odd ? c[i][j][0] : c[i][j][2];
                float u1 = odd ? c[i][j][1] : c[i][j][3];
                float rx0 = __shfl_xor_sync(0xffffffffu, u0, 1);
                float rx1 = __shfl_xor_sync(0xffffffffu, u1, 1);
                float gi, gf, gg, go;
                if (!odd) { gi = c[i][j][0]; gf = c[i][j][1]; gg = rx0; go = rx1; }
                else      { gi = rx0; gf = rx1; gg = c[i][j][2]; go = c[i][j][3]; }
                gi += bb[j].x; gf += bb[j].y; gg += bb[j].z; go += bb[j].w;
                float i_ = fsig(gi);
                float f_ = fsig(gf);
                float g_ = ftanh(gg);
                float o_ = fsig(go);
                int ci = i * 2 + j;
                float cn = f_ * creg[ci] + i_ * g_;
                creg[ci] = cn;
                hv[i][j] = o_ * ftanh(cn);
            }
        }
        // exchange across lane^2 so each thread holds adjacent units {unit2, unit2+1}
        uint32_t pkr[2];
        #pragma unroll
        for (int i = 0; i < 2; i++) {
            float send = b2 ? hv[i][0] : hv[i][1];
            float recv = __shfl_xor_sync(0xffffffffu, send, 2);
            pkr[i] = b2 ? pack_h2(recv, hv[i][1]) : pack_h2(hv[i][0], recv);
        }
        // packed half2 stores: hn (L2-targeted) + hs archive
        #pragma unroll
        for (int i = 0; i < 2; i++) {
            __stcg((__half2*)(hn + (size_t)erow[i] * HID + unit2),
                   *reinterpret_cast<__half2*>(&pkr[i]));
        }

        int bi = gid * TSEQ + t;
        if (t < TSEQ - 1) {
            __syncthreads();
            if (tid == 0) bar_arrive_release(&bar[bi]);   // release orders hn stores
            // prefetch next x tile while peers arrive
            #pragma unroll
            for (int itr = 0; itr < 4; itr++) {
                int gi = itr * 256 + tid;
                int row = gi >> 5;
                int c4 = gi & 31;
                float4 v = __ldg((const float4*)(X + ((size_t)(m0 + row) * TSEQ + (t + 1)) * DIN + c4 * 4));
                uint2 pk = { pack_h2(v.x, v.y), pack_h2(v.z, v.w) };
                *(uint2*)&sX[row][c4 * 4] = pk;
            }
        }
        #pragma unroll
        for (int i = 0; i < 2; i++)
            *(__half2*)(hs + ((size_t)erow[i] * TSEQ + t) * HID + unit2) =
                *reinterpret_cast<__half2*>(&pkr[i]);
        if (t < TSEQ - 1) {
            if (tid == 0) { while (bar_poll_acquire(&bar[bi]) < NGRP) {} }
            __syncthreads();
        }
    }
}

// ---------------- medium GEMM with register double-buffering --------------------------
template <bool TRANS, bool RELU>
__global__ __launch_bounds__(256) void gemm_med(
    const float* __restrict__ A, const float* __restrict__ W,
    const float* __restrict__ bias, float* __restrict__ C,
    int M, int N, int K, int lda, int ldw, int ldc) {
    __shared__ float sA[16][68];
    __shared__ float sW[16][68];
    int m0 = blockIdx.y * 64, n0 = blockIdx.x * 64;
    int tid = threadIdx.x;
    int tx = tid & 15, ty = tid >> 4;
    float acc[4][4] = {};
    float pa[4], pw[4];

    #pragma unroll
    for (int i = 0; i < 4; i++) {
        int idx = tid + i * 256;
        int r = idx >> 4, k = idx & 15;
        int mm = m0 + r, kk = k;
        pa[i] = (mm < M && kk < K) ? A[(size_t)mm * lda + kk] : 0.f;
        int nn = n0 + r;
        float v = 0.f;
        if (TRANS) { if (kk < K && nn < N) v = W[(size_t)kk * ldw + nn]; }
        else       { if (nn < N && kk < K) v = W[(size_t)nn * ldw + kk]; }
        pw[i] = v;
    }
    for (int k0 = 0; k0 < K; k0 += 16) {
        #pragma unroll
        for (int i = 0; i < 4; i++) {
            int idx = tid + i * 256;
            int r = idx >> 4, k = idx & 15;
            sA[k][r] = pa[i];
            sW[k][r] = pw[i];
        }
        __syncthreads();
        if (k0 + 16 < K) {
            #pragma unroll
            for (int i = 0; i < 4; i++) {
                int idx = tid + i * 256;
                int r = idx >> 4, k = idx & 15;
                int mm = m0 + r, kk = k0 + 16 + k;
                pa[i] = (mm < M && kk < K) ? A[(size_t)mm * lda + kk] : 0.f;
                int nn = n0 + r;
                float v = 0.f;
                if (TRANS) { if (kk < K && nn < N) v = W[(size_t)kk * ldw + nn]; }
                else       { if (nn < N && kk < K) v = W[(size_t)nn * ldw + kk]; }
                pw[i] = v;
            }
        }
        #pragma unroll
        for (int k = 0; k < 16; k++) {
            float4 a = *(const float4*)&sA[k][ty * 4];
            float4 b = *(const float4*)&sW[k][tx * 4];
            acc[0][0] += a.x * b.x; acc[0][1] += a.x * b.y; acc[0][2] += a.x * b.z; acc[0][3] += a.x * b.w;
            acc[1][0] += a.y * b.x; acc[1][1] += a.y * b.y; acc[1][2] += a.y * b.z; acc[1][3] += a.y * b.w;
            acc[2][0] += a.z * b.x; acc[2][1] += a.z * b.y; acc[2][2] += a.z * b.z; acc[2][3] += a.z * b.w;
            acc[3][0] += a.w * b.x; acc[3][1] += a.w * b.y; acc[3][2] += a.w * b.z; acc[3][3] += a.w * b.w;
        }
        __syncthreads();
    }
    #pragma unroll
    for (int r = 0; r < 4; r++) {
        int m = m0 + ty * 4 + r;
        if (m >= M) continue;
        #pragma unroll
        for (int cc = 0; cc < 4; cc++) {
            int n = n0 + tx * 4 + cc;
            if (n >= N) continue;
            float v = acc[r][cc];
            if (bias) v += bias[n];
            if (RELU) v = fmaxf(v, 0.f);
            C[(size_t)m * ldc + n] = v;
        }
    }
}

// ---------------- fused attention over fp16 hs (512 threads) -------------------------
__global__ __launch_bounds__(512) void attn_kernel(
    const __half* __restrict__ hs, const float* __restrict__ qk,
    float* __restrict__ hbar) {
    int b = blockIdx.x;
    __shared__ float sc[TSEQ];
    __shared__ float red[256];
    __shared__ float sqk[HID];
    __shared__ float part[2][256];
    int tid = threadIdx.x;
    int lane = tid & 31, w = tid >> 5;
    if (tid < HID) sqk[tid] = qk[b * HID + tid];
    __syncthreads();
    for (int t = w; t < TSEQ; t += 16) {
        const __half2* hrow = (const __half2*)(hs + ((size_t)b * TSEQ + t) * HID);
        float p = 0.f;
        #pragma unroll
        for (int j = 0; j < 4; j++) {
            int h2i = lane + 32 * j;
            float2 hv = __half22float2(hrow[h2i]);
            p += hv.x * sqk[2 * h2i] + hv.y * sqk[2 * h2i + 1];
        }
        #pragma unroll
        for (int o = 16; o > 0; o >>= 1) p += __shfl_down_sync(0xffffffffu, p, o);
        if (lane == 0) sc[t] = p;
    }
    __syncthreads();
    float scale = 1.0f / sqrtf((float)EDIM);
    float v = (tid < 256) ? sc[tid] * scale : -1e30f;
    if (tid < 256) red[tid] = v;
    __syncthreads();
    for (int s = 128; s > 0; s >>= 1) { if (tid < s) red[tid] = fmaxf(red[tid], red[tid + s]); __syncthreads(); }
    float mx = red[0]; __syncthreads();
    float ev = (tid < 256) ? __expf(v - mx) : 0.f;
    if (tid < 256) red[tid] = ev;
    __syncthreads();
    for (int s = 128; s > 0; s >>= 1) { if (tid < s) red[tid] += red[tid + s]; __syncthreads(); }
    float sum = red[0]; __syncthreads();
    if (tid < 256) sc[tid] = __fdividef(ev, sum);
    __syncthreads();
    int h = tid & 255, half = tid >> 8;
    const __half* hb = hs + (size_t)b * TSEQ * HID;
    float acc = 0.f;
    for (int t = half * 128; t < (half + 1) * 128; t++)
        acc += sc[t] * __half2float(hb[(size_t)t * HID + h]);
    part[half][h] = acc;
    __syncthreads();
    if (tid < 256) hbar[b * HID + tid] = part[0][tid] + part[1][tid];
}

// ---------------- concat helpers ----------------
__global__ void sf_build(const __half* __restrict__ hs, const float* __restrict__ s,
                         float* __restrict__ sf) {
    int idx = blockIdx.x * blockDim.x + threadIdx.x;
    if (idx >= BATCH * EDIM) return;
    int b = idx / EDIM, j = idx % EDIM;
    sf[idx] = (j < HID) ? __half2float(hs[((size_t)b * TSEQ + (TSEQ - 1)) * HID + j])
                        : s[b * FDIM + (j - HID)];
}
__global__ void scopy(const float* __restrict__ s, float* __restrict__ merged) {
    int idx = blockIdx.x * blockDim.x + threadIdx.x;
    if (idx >= BATCH * FDIM) return;
    int b = idx >> 6, f = idx & 63;
    merged[(size_t)b * NMERG + EDIM + f] = s[idx];
}

// ---------------- 10-qubit VQC ----------------
struct c2f { float x, y; };
__device__ __forceinline__ c2f cmul(c2f a, c2f b) { return { a.x * b.x - a.y * b.y, a.x * b.y + a.y * b.x }; }
__device__ __forceinline__ c2f cadd(c2f a, c2f b) { return { a.x + b.x, a.y + b.y }; }
__device__ __forceinline__ void matmul2(c2f C[2][2], const c2f A[2][2], const c2f B[2][2]) {
    #pragma unroll
    for (int i = 0; i < 2; i++)
        #pragma unroll
        for (int j = 0; j < 2; j++)
            C[i][j] = cadd(cmul(A[i][0], B[0][j]), cmul(A[i][1], B[1][j]));
}
__device__ __forceinline__ int cnot_ring_gather(int i) {
    int j = i;
    j ^= (j & 1) << 9;
    #pragma unroll
    for (int k = 9; k >= 1; k--)
        j ^= ((j >> (10 - k)) & 1) << (9 - k);
    return j;
}

__global__ __launch_bounds__(512) void vqc_kernel(float* __restrict__ merged,
                                                  const float* __restrict__ qw) {
    int b = blockIdx.x;
    __shared__ c2f psi[1024];
    __shared__ float sang[40];
    __shared__ float wsum[16][10];
    int tid = threadIdx.x;
    int lane = tid & 31, w = tid >> 5;
    const float PI_F = 3.14159265358979323846f;
    psi[tid] = { 0.03125f, 0.f };
    psi[tid + 512] = { 0.03125f, 0.f };
    if (tid < 40) sang[tid] = ftanh(merged[(size_t)b * NMERG + tid]) * PI_F;
    __syncthreads();

    int gidx0 = cnot_ring_gather(tid);
    int gidx1 = cnot_ring_gather(tid + 512);

    for (int layer = 0; layer < 4; layer++) {
        for (int q = 0; q < 10; q++) {
            int idx = layer * 10 + q;
            float a = sang[idx];
            float w0 = qw[idx * 3 + 0], w1 = qw[idx * 3 + 1], w2 = qw[idx * 3 + 2];
            float ch, sh; __sincosf(0.5f * a, &sh, &ch);
            c2f Rx[2][2] = { { {ch, 0.f}, {0.f, -sh} }, { {0.f, -sh}, {ch, 0.f} } };
            c2f Rya[2][2] = { { {ch, 0.f}, {-sh, 0.f} }, { {sh, 0.f}, {ch, 0.f} } };
            c2f T1[2][2]; matmul2(T1, Rya, Rx);
            float c0, s0; __sincosf(0.5f * w0, &s0, &c0);
            c2f Rz0[2][2] = { { {c0, -s0}, {0.f, 0.f} }, { {0.f, 0.f}, {c0, s0} } };
            c2f T2[2][2]; matmul2(T2, Rz0, T1);
            float c1, s1; __sincosf(0.5f * w1, &s1, &c1);
            c2f Ry1[2][2] = { { {c1, 0.f}, {-s1, 0.f} }, { {s1, 0.f}, {c1, 0.f} } };
            c2f T3[2][2]; matmul2(T3, Ry1, T2);
            float c2r, s2r; __sincosf(0.5f * w2, &s2r, &c2r);
            c2f Rz2[2][2] = { { {c2r, -s2r}, {0.f, 0.f} }, { {0.f, 0.f}, {c2r, s2r} } };
            c2f U[2][2]; matmul2(U, Rz2, T3);

            int bq = 9 - q;
            int low = tid & ((1 << bq) - 1);
            int i0 = ((tid >> bq) << (bq + 1)) | low;
            int i1 = i0 | (1 << bq);
            __syncthreads();
            c2f a0 = psi[i0], a1 = psi[i1];
            psi[i0] = cadd(cmul(U[0][0], a0), cmul(U[0][1], a1));
            psi[i1] = cadd(cmul(U[1][0], a0), cmul(U[1][1], a1));
        }
        __syncthreads();
        c2f v0 = psi[gidx0], v1 = psi[gidx1];
        __syncthreads();
        psi[tid] = v0;
        psi[tid + 512] = v1;
    }
    __syncthreads();
    c2f p0 = psi[tid], p1 = psi[tid + 512];
    float n0 = p0.x * p0.x + p0.y * p0.y;
    float n1 = p1.x * p1.x + p1.y * p1.y;
    float acc[10];
    #pragma unroll
    for (int k = 0; k < 10; k++) {
        int bp_ = 9 - k;
        float s0v = ((tid >> bp_) & 1) ? -n0 : n0;
        float s1v = (((tid + 512) >> bp_) & 1) ? -n1 : n1;
        acc[k] = s0v + s1v;
        #pragma unroll
        for (int o = 16; o > 0; o >>= 1) acc[k] += __shfl_down_sync(0xffffffffu, acc[k], o);
    }
    if (lane == 0)
        #pragma unroll
        for (int k = 0; k < 10; k++) wsum[w][k] = acc[k];
    __syncthreads();
    if (tid < 10) {
        float a = 0.f;
        #pragma unroll
        for (int ww = 0; ww < 16; ww++) a += wsum[ww][tid];
        merged[(size_t)b * NMERG + DM + tid] = a;
    }
}

// ---------------- host launch ----------------
#define GETSYM(p, sym) do { void* _t = nullptr; cudaGetSymbolAddress(&_t, sym); (p) = (float*)_t; } while (0)

extern "C" void kernel_launch(void* const* d_in, const int* in_sizes, int n_in,
                              void* d_out, int out_size) {
    const float* s          = (const float*)d_in[0];
    const float* lstm_s     = (const float*)d_in[1];
    const float* W_ih       = (const float*)d_in[2];
    const float* W_hh       = (const float*)d_in[3];
    const float* b_ih       = (const float*)d_in[4];
    const float* b_hh       = (const float*)d_in[5];
    const float* proj_W     = (const float*)d_in[6];
    const float* proj_b     = (const float*)d_in[7];
    const float* in_proj_W  = (const float*)d_in[8];
    const float* in_proj_b  = (const float*)d_in[9];
    const float* out_proj_W = (const float*)d_in[10];
    const float* out_proj_b = (const float*)d_in[11];
    const float* qweights   = (const float*)d_in[12];
    const float* W1         = (const float*)d_in[13];
    const float* b1         = (const float*)d_in[14];
    const float* W2         = (const float*)d_in[15];
    const float* b2         = (const float*)d_in[16];
    float* out = (float*)d_out;

    float *sf, *qk, *Mkp, *MA1, *Amat, *P, *cqk;
    float *aconst, *hbar, *merged, *x1;
    __half *hbuf, *hs;
    int* bar;
    { void* _t = nullptr; cudaGetSymbolAddress(&_t, d_hbuf); hbuf = (__half*)_t; }
    { void* _t = nullptr; cudaGetSymbolAddress(&_t, d_hs); hs = (__half*)_t; }
    GETSYM(sf, d_sf);
    GETSYM(qk, d_qk);   GETSYM(Mkp, d_Mkp); GETSYM(MA1, d_MA1);
    GETSYM(Amat, d_Amat); GETSYM(P, d_P);   GETSYM(cqk, d_cqk);
    GETSYM(aconst, d_aconst);
    GETSYM(hbar, d_hbar);
    GETSYM(merged, d_merged); GETSYM(x1, d_x1);
    { void* _t = nullptr; cudaGetSymbolAddress(&_t, d_bar); bar = (int*)_t; }

    cudaMemsetAsync(bar, 0, (16 * TSEQ + 1) * sizeof(int));

    // merged[:, EDIM:DM] = s (input-only dependency)
    scopy<<<(BATCH * FDIM + 255) / 256, 256>>>(s, merged);

    // persistent fused LSTM + hidden attention-weight precompose
    lstm_persist<<<NBLK + NPRE, 256>>>(lstm_s, W_ih, W_hh, b_ih, b_hh, hs, hbuf, bar,
                                       in_proj_W, in_proj_b, proj_W, proj_b,
                                       out_proj_W, out_proj_b,
                                       Mkp, MA1, Amat, P, cqk, aconst);

    // state_full = [h_last, s]; qk = sf @ P + cqk
    sf_build<<<(BATCH * EDIM + 255) / 256, 256>>>(hs, s, sf);
    gemm_med<true, false><<<dim3(4, 8), 256>>>(sf, P, cqk, qk, BATCH, HID, EDIM, EDIM, HID, HID);

    // fused attention over hs
    attn_kernel<<<BATCH, 512>>>(hs, qk, hbar);

    // attn_out written directly into merged[:, :EDIM]
    gemm_med<false, false><<<dim3(5, 8), 256>>>(hbar, Amat, aconst, merged, BATCH, EDIM, HID, HID, HID, NMERG);

    // VQC (writes qfeat into merged[:, DM:])
    vqc_kernel<<<BATCH, 512>>>(merged, qweights);

    // MLP
    gemm_med<false, true><<<dim3(8, 8), 256>>>(merged, W1, b1, x1, BATCH, NL1, NMERG, NMERG, NMERG, NL1);
    gemm_med<false, false><<<dim3(1, 8), 256>>>(x1, W2, b2, out, BATCH, NACT, NL1, NL1, NL1, NACT);
}